// round 1
// baseline (speedup 1.0000x reference)
#include <cuda_runtime.h>
#include <math.h>

#define NQ 20000
#define MP 20000
#define KN 32
#define DF 64
#define HIDN 64
#define OUTN 192
#define PPFO 64

#define THREADS 512
#define WARPS_PER_CTA (THREADS / 32)
#define GRID 148

// shared layout (floats):
// sW1 256 | sb1 64 | sW2 4096 | sb2 64 | sW3T 4096 | sb3 64 | sWgT 12288 | sbg 192 | sWvT 12288
// then per-warp: hb 64 | pm 64 | agg 192  (320 floats each)
#define SM_WEIGHTS (256 + 64 + 4096 + 64 + 4096 + 64 + 12288 + 192 + 12288)
#define SM_PER_WARP 320
#define SM_FLOATS (SM_WEIGHTS + WARPS_PER_CTA * SM_PER_WARP)

__device__ __forceinline__ float angle_fn(float ax, float ay, float az,
                                          float bx, float by, float bz) {
    float dt = ax * bx + ay * by + az * bz;
    float cx = ay * bz - az * by;
    float cy = az * bx - ax * bz;
    float cz = ax * by - ay * bx;
    float xn = sqrtf(cx * cx + cy * cy + cz * cz);
    float xs;
    if (fabsf(dt) < 1e-8f)
        xs = (dt > 0.f) ? 1e-8f : ((dt < 0.f) ? -1e-8f : 0.f);
    else
        xs = dt;
    return atan2f(xn, xs) * 0.31830988618379067f;  // 1/pi
}

__global__ __launch_bounds__(THREADS, 1)
void ppf_attn_kernel(const float* __restrict__ q_pts,
                     const float* __restrict__ s_pts,
                     const float* __restrict__ s_feats,
                     const int*   __restrict__ nbr,
                     const float* __restrict__ normals,
                     const float* __restrict__ W1, const float* __restrict__ b1,
                     const float* __restrict__ W2, const float* __restrict__ b2,
                     const float* __restrict__ W3, const float* __restrict__ b3,
                     const float* __restrict__ Wg, const float* __restrict__ bg,
                     const float* __restrict__ Wv,
                     float* __restrict__ out) {
    extern __shared__ float sm[];
    float* sW1  = sm;                 // 256   [j*4+i]
    float* sb1  = sW1  + 256;         // 64
    float* sW2  = sb1  + 64;          // 4096  [j*64+i]
    float* sb2  = sW2  + 4096;        // 64
    float* sW3T = sb2  + 64;          // 4096  [i*64+j] = W3[j][i]
    float* sb3  = sW3T + 4096;        // 64
    float* sWgT = sb3  + 64;          // 12288 [j*192+o] = Wg[o][j]
    float* sbg  = sWgT + 12288;       // 192
    float* sWvT = sbg  + 192;         // 12288 [d*192+o] = Wv[o][d]
    float* swarp = sWvT + 12288;

    const int tid = threadIdx.x;

    // ---- stage weights into shared (transpose the lane-row-indexed ones) ----
    for (int i = tid; i < 256; i += THREADS)  sW1[i] = W1[i];
    for (int i = tid; i < 64;  i += THREADS)  { sb1[i] = b1[i]; sb2[i] = b2[i]; sb3[i] = b3[i]; }
    for (int i = tid; i < 4096; i += THREADS) sW2[i] = W2[i];
    for (int i = tid; i < 4096; i += THREADS) { int j = i >> 6, k = i & 63; sW3T[k * 64 + j] = W3[i]; }
    for (int i = tid; i < 12288; i += THREADS) { int o = i >> 6, j = i & 63; sWgT[j * 192 + o] = Wg[i]; }
    for (int i = tid; i < 12288; i += THREADS) { int o = i >> 6, d = i & 63; sWvT[d * 192 + o] = Wv[i]; }
    for (int i = tid; i < 192; i += THREADS)  sbg[i] = bg[i];
    __syncthreads();

    const int warp = tid >> 5;
    const int lane = tid & 31;
    float* shb  = swarp + warp * SM_PER_WARP;      // 64
    float* spm  = shb + 64;                        // 64
    float* sagg = spm + 64;                        // 192

    const int gw = blockIdx.x * WARPS_PER_CTA + warp;
    const int nw = gridDim.x * WARPS_PER_CTA;
    const unsigned FULL = 0xffffffffu;

    for (int q = gw; q < NQ; q += nw) {
        // ---- gather + PPF (one lane = one neighbor) ----
        const int idxk = nbr[q * KN + lane];
        const int idx0 = __shfl_sync(FULL, idxk, 0);

        const float px = q_pts[q * 3 + 0];
        const float py = q_pts[q * 3 + 1];
        const float pz = q_pts[q * 3 + 2];
        const float pnx = normals[idx0 * 3 + 0];
        const float pny = normals[idx0 * 3 + 1];
        const float pnz = normals[idx0 * 3 + 2];
        const float sx = s_pts[idxk * 3 + 0];
        const float sy = s_pts[idxk * 3 + 1];
        const float sz = s_pts[idxk * 3 + 2];
        const float nnx = normals[idxk * 3 + 0];
        const float nny = normals[idxk * 3 + 1];
        const float nnz = normals[idxk * 3 + 2];

        const float vx = sx - px, vy = sy - py, vz = sz - pz;
        const float dpp = sqrtf(vx * vx + vy * vy + vz * vz);
        const float a1 = angle_fn(pnx, pny, pnz, vx, vy, vz);
        const float a2 = angle_fn(nnx, nny, nnz, vx, vy, vz);
        const float a3 = angle_fn(pnx, pny, pnz, nnx, nny, nnz);

        // ---- layer 1: h1[64] in registers ----
        float h1[64];
        const float4* w1v = (const float4*)sW1;
#pragma unroll
        for (int j = 0; j < 64; j++) {
            float4 w = w1v[j];
            float v = sb1[j];
            v = fmaf(dpp, w.x, v);
            v = fmaf(a1, w.y, v);
            v = fmaf(a2, w.z, v);
            v = fmaf(a3, w.w, v);
            h1[j] = fmaxf(v, 0.f);
        }

        // ---- layer 2 + mean over K (butterfly reduce), mean commutes past W3 ----
        for (int j = 0; j < 64; j += 2) {
            float acc0 = sb2[j], acc1 = sb2[j + 1];
            const float4* r0 = (const float4*)(sW2 + j * 64);
            const float4* r1 = r0 + 16;
#pragma unroll
            for (int i = 0; i < 16; i++) {
                float4 w0 = r0[i];
                float4 w1w = r1[i];
                acc0 = fmaf(h1[4 * i + 0], w0.x, acc0);
                acc0 = fmaf(h1[4 * i + 1], w0.y, acc0);
                acc0 = fmaf(h1[4 * i + 2], w0.z, acc0);
                acc0 = fmaf(h1[4 * i + 3], w0.w, acc0);
                acc1 = fmaf(h1[4 * i + 0], w1w.x, acc1);
                acc1 = fmaf(h1[4 * i + 1], w1w.y, acc1);
                acc1 = fmaf(h1[4 * i + 2], w1w.z, acc1);
                acc1 = fmaf(h1[4 * i + 3], w1w.w, acc1);
            }
            acc0 = fmaxf(acc0, 0.f);
            acc1 = fmaxf(acc1, 0.f);
#pragma unroll
            for (int off = 16; off > 0; off >>= 1) {
                acc0 += __shfl_xor_sync(FULL, acc0, off);
                acc1 += __shfl_xor_sync(FULL, acc1, off);
            }
            if (lane == 0) {
                shb[j]     = acc0 * (1.f / KN);
                shb[j + 1] = acc1 * (1.f / KN);
            }
        }
        __syncwarp();

        // ---- layer 3 on the mean: ppf_mod[64], 2 outputs per lane ----
        {
            float a0 = sb3[lane], a1v = sb3[lane + 32];
#pragma unroll 8
            for (int i = 0; i < 64; i++) {
                float hv = shb[i];
                a0  = fmaf(hv, sW3T[i * 64 + lane],      a0);
                a1v = fmaf(hv, sW3T[i * 64 + lane + 32], a1v);
            }
            spm[lane]      = a0;
            spm[lane + 32] = a1v;
        }
        __syncwarp();

        // ---- gate[192]: 6 outputs per lane ----
        float g[6];
        {
            float acc[6];
#pragma unroll
            for (int r = 0; r < 6; r++) acc[r] = sbg[lane + 32 * r];
#pragma unroll 4
            for (int j = 0; j < 64; j++) {
                float pv = spm[j];
                const float* wr = sWgT + j * 192 + lane;
#pragma unroll
                for (int r = 0; r < 6; r++) acc[r] = fmaf(pv, wr[32 * r], acc[r]);
            }
#pragma unroll
            for (int r = 0; r < 6; r++) g[r] = 1.f / (1.f + expf(-acc[r]));
        }

        // ---- mean of gathered neighbor features (coalesced float2) ----
        {
            float2 fa0 = {0.f, 0.f}, fa1 = {0.f, 0.f}, fa2 = {0.f, 0.f};
#pragma unroll 4
            for (int k = 0; k < KN; k++) {
                int row = __shfl_sync(FULL, idxk, k);
                const float2* base = (const float2*)(s_feats + (size_t)row * 192);
                float2 v0 = base[lane];
                float2 v1 = base[lane + 32];
                float2 v2 = base[lane + 64];
                fa0.x += v0.x; fa0.y += v0.y;
                fa1.x += v1.x; fa1.y += v1.y;
                fa2.x += v2.x; fa2.y += v2.y;
            }
            float2* aggv = (float2*)sagg;
            const float inv = 1.f / KN;
            aggv[lane]      = make_float2(fa0.x * inv, fa0.y * inv);
            aggv[lane + 32] = make_float2(fa1.x * inv, fa1.y * inv);
            aggv[lane + 64] = make_float2(fa2.x * inv, fa2.y * inv);
        }
        __syncwarp();

        // ---- transformed = Wv @ agg, scaled by gate; write out ----
        {
            float t0[6], t1[6], t2[6];
#pragma unroll
            for (int r = 0; r < 6; r++) { t0[r] = 0.f; t1[r] = 0.f; t2[r] = 0.f; }
#pragma unroll 4
            for (int dd = 0; dd < 64; dd++) {
                float a0v = sagg[3 * dd + 0];
                float a1v = sagg[3 * dd + 1];
                float a2v = sagg[3 * dd + 2];
                const float* wr = sWvT + dd * 192 + lane;
#pragma unroll
                for (int r = 0; r < 6; r++) {
                    float w = wr[32 * r];
                    t0[r] = fmaf(w, a0v, t0[r]);
                    t1[r] = fmaf(w, a1v, t1[r]);
                    t2[r] = fmaf(w, a2v, t2[r]);
                }
            }
            float* ob = out + (size_t)q * (OUTN * 3);
#pragma unroll
            for (int r = 0; r < 6; r++) {
                int o = lane + 32 * r;
                ob[o * 3 + 0] = t0[r] * g[r];
                ob[o * 3 + 1] = t1[r] * g[r];
                ob[o * 3 + 2] = t2[r] * g[r];
            }
        }
        __syncwarp();  // protect per-warp shared before next iteration
    }
}

extern "C" void kernel_launch(void* const* d_in, const int* in_sizes, int n_in,
                              void* d_out, int out_size) {
    const float* q_pts   = (const float*)d_in[0];
    const float* s_pts   = (const float*)d_in[1];
    const float* s_feats = (const float*)d_in[2];
    const int*   nbr     = (const int*)  d_in[3];
    const float* normals = (const float*)d_in[4];
    const float* W1 = (const float*)d_in[5];
    const float* b1 = (const float*)d_in[6];
    const float* W2 = (const float*)d_in[7];
    const float* b2 = (const float*)d_in[8];
    const float* W3 = (const float*)d_in[9];
    const float* b3 = (const float*)d_in[10];
    const float* Wg = (const float*)d_in[11];
    const float* bg = (const float*)d_in[12];
    const float* Wv = (const float*)d_in[13];
    float* out = (float*)d_out;

    static_assert(SM_FLOATS * 4 < 227 * 1024, "smem overflow");
    size_t smem = SM_FLOATS * sizeof(float);
    cudaFuncSetAttribute(ppf_attn_kernel,
                         cudaFuncAttributeMaxDynamicSharedMemorySize, (int)smem);

    ppf_attn_kernel<<<GRID, THREADS, smem>>>(
        q_pts, s_pts, s_feats, nbr, normals,
        W1, b1, W2, b2, W3, b3, Wg, bg, Wv, out);
}

// round 2
// speedup vs baseline: 1.1140x; 1.1140x over previous
#include <cuda_runtime.h>
#include <math.h>

typedef unsigned long long ull;

#define NQ 20000
#define KN 32
#define OUTN 192
#define THREADS 512
#define NW 16
#define GRID 148

// ---- shared memory layout (float offsets) ----
#define OFF_W1   0        // 256   [j*4+i]
#define OFF_B1   256      // 64
#define OFF_B2   320      // 64
#define OFF_B3   384      // 64
#define OFF_BG   448      // 192
#define OFF_W2T  640      // 64 x 72   [i*72 + j] = W2[j][i]
#define OFF_W3T  5248     // 64 x 68   [i*68 + o] = W3[o][i]
#define OFF_WGT  9600     // 64 x 196  [j*196 + o] = Wg[o][j]
#define OFF_WVT  22144    // 64 x 196  [d*196 + o] = Wv[o][d]
#define OFF_PM   34688    // 64 x 18   [j*18 + q]
#define OFF_AGG  35840    // 64 x 50   [d*50 + q*3 + t]
#define OFF_GATE 39040    // 16 x 200  [q*200 + o]
#define OFF_WARP 42240    // per warp 608 floats: h1s[16*34]=544 then shb[64]
#define SM_FLOATS (OFF_WARP + NW * 608)

__device__ __forceinline__ ull pk2(float lo, float hi) {
    ull r; asm("mov.b64 %0, {%1, %2};" : "=l"(r) : "f"(lo), "f"(hi)); return r;
}
__device__ __forceinline__ void upk2(ull v, float& lo, float& hi) {
    asm("mov.b64 {%0, %1}, %2;" : "=f"(lo), "=f"(hi) : "l"(v));
}
__device__ __forceinline__ ull fma2(ull a, ull b, ull c) {
    ull d; asm("fma.rn.f32x2 %0, %1, %2, %3;" : "=l"(d) : "l"(a), "l"(b), "l"(c)); return d;
}

__device__ __forceinline__ float angle_fn(float ax, float ay, float az,
                                          float bx, float by, float bz) {
    float dt = ax * bx + ay * by + az * bz;
    float cx = ay * bz - az * by;
    float cy = az * bx - ax * bz;
    float cz = ax * by - ay * bx;
    float xn = sqrtf(cx * cx + cy * cy + cz * cz);
    float xs;
    if (fabsf(dt) < 1e-8f)
        xs = (dt > 0.f) ? 1e-8f : ((dt < 0.f) ? -1e-8f : 0.f);
    else
        xs = dt;
    return atan2f(xn, xs) * 0.31830988618379067f;  // 1/pi
}

__global__ __launch_bounds__(THREADS, 1)
void ppf_attn_kernel(const float* __restrict__ q_pts,
                     const float* __restrict__ s_pts,
                     const float* __restrict__ s_feats,
                     const int*   __restrict__ nbr,
                     const float* __restrict__ normals,
                     const float* __restrict__ W1, const float* __restrict__ b1,
                     const float* __restrict__ W2, const float* __restrict__ b2,
                     const float* __restrict__ W3, const float* __restrict__ b3,
                     const float* __restrict__ Wg, const float* __restrict__ bg,
                     const float* __restrict__ Wv,
                     float* __restrict__ out) {
    extern __shared__ float sm[];
    const int tid = threadIdx.x;

    // ---- stage weights (once per CTA) ----
    for (int i = tid; i < 256; i += THREADS) sm[OFF_W1 + i] = W1[i];
    for (int i = tid; i < 64; i += THREADS) {
        sm[OFF_B1 + i] = b1[i]; sm[OFF_B2 + i] = b2[i]; sm[OFF_B3 + i] = b3[i];
    }
    for (int i = tid; i < 192; i += THREADS) sm[OFF_BG + i] = bg[i];
    for (int l = tid; l < 4096; l += THREADS) {     // W2[j][i] -> [i*72 + j]
        int j = l >> 6, i = l & 63;
        sm[OFF_W2T + i * 72 + j] = W2[l];
    }
    for (int l = tid; l < 4096; l += THREADS) {     // W3[o][i] -> [i*68 + o]
        int o = l >> 6, i = l & 63;
        sm[OFF_W3T + i * 68 + o] = W3[l];
    }
    for (int l = tid; l < 12288; l += THREADS) {    // Wg[o][j] -> [j*196 + o]
        int o = l >> 6, j = l & 63;
        sm[OFF_WGT + j * 196 + o] = Wg[l];
    }
    for (int l = tid; l < 12288; l += THREADS) {    // Wv[o][d] -> [d*196 + o]
        int o = l >> 6, d = l & 63;
        sm[OFF_WVT + d * 196 + o] = Wv[l];
    }
    __syncthreads();

    const int w = tid >> 5;
    const int lane = tid & 31;
    const unsigned FULL = 0xffffffffu;
    float* h1s = sm + OFF_WARP + w * 608;   // 16 x 34
    float* shb = h1s + 544;                 // 64

    const int j0 = (lane >> 2) * 8;   // layer2 j-tile base
    const int k0 = (lane & 3) * 8;    // layer2 k-tile base

    for (int base = blockIdx.x * NW; base < NQ; base += GRID * NW) {
        const int q = base + w;

        // ================= Phase A (per-warp, query q) =================
        const int idxk = nbr[q * KN + lane];
        const int idx0 = __shfl_sync(FULL, idxk, 0);

        const float px = q_pts[q * 3 + 0], py = q_pts[q * 3 + 1], pz = q_pts[q * 3 + 2];
        const float pnx = normals[idx0 * 3 + 0], pny = normals[idx0 * 3 + 1], pnz = normals[idx0 * 3 + 2];
        const float sx = s_pts[idxk * 3 + 0], sy = s_pts[idxk * 3 + 1], sz = s_pts[idxk * 3 + 2];
        const float nnx = normals[idxk * 3 + 0], nny = normals[idxk * 3 + 1], nnz = normals[idxk * 3 + 2];

        const float vx = sx - px, vy = sy - py, vz = sz - pz;
        const float dpp = sqrtf(vx * vx + vy * vy + vz * vz);
        const float a1 = angle_fn(pnx, pny, pnz, vx, vy, vz);
        const float a2 = angle_fn(nnx, nny, nnz, vx, vy, vz);
        const float a3 = angle_fn(pnx, pny, pnz, nnx, nny, nnz);

        // layer2 accumulators: 8j x 8k tile, packed pairs along k
        ull acc[8][4];
#pragma unroll
        for (int jj = 0; jj < 8; jj++) {
            float bv = sm[OFF_B2 + j0 + jj];
            ull bp = pk2(bv, bv);
#pragma unroll
            for (int s = 0; s < 4; s++) acc[jj][s] = bp;
        }

        // 4 passes of 16 i: layer1 quarter -> stage -> GEMM quarter
        for (int p = 0; p < 4; p++) {
            const float4* w1v = (const float4*)(sm + OFF_W1) + p * 16;
            const float* b1p = sm + OFF_B1 + p * 16;
#pragma unroll
            for (int ii = 0; ii < 16; ii++) {
                float4 wv4 = w1v[ii];
                float v = b1p[ii];
                v = fmaf(dpp, wv4.x, v);
                v = fmaf(a1, wv4.y, v);
                v = fmaf(a2, wv4.z, v);
                v = fmaf(a3, wv4.w, v);
                h1s[ii * 34 + lane] = fmaxf(v, 0.f);
            }
            __syncwarp();
#pragma unroll 2
            for (int ii = 0; ii < 16; ii++) {
                const float* wr = sm + OFF_W2T + (p * 16 + ii) * 72 + j0;
                float4 wa = *(const float4*)wr;
                float4 wb = *(const float4*)(wr + 4);
                const float* hr = h1s + ii * 34 + k0;
                ull h0 = *(const ull*)(hr + 0);
                ull h1p = *(const ull*)(hr + 2);
                ull h2p = *(const ull*)(hr + 4);
                ull h3p = *(const ull*)(hr + 6);
                float wvv[8] = {wa.x, wa.y, wa.z, wa.w, wb.x, wb.y, wb.z, wb.w};
#pragma unroll
                for (int jj = 0; jj < 8; jj++) {
                    ull wd = pk2(wvv[jj], wvv[jj]);
                    acc[jj][0] = fma2(wd, h0, acc[jj][0]);
                    acc[jj][1] = fma2(wd, h1p, acc[jj][1]);
                    acc[jj][2] = fma2(wd, h2p, acc[jj][2]);
                    acc[jj][3] = fma2(wd, h3p, acc[jj][3]);
                }
            }
            __syncwarp();
        }

        // relu + sum over this lane's 8 k, then over the 4 lanes sharing j0
        float jsum[8];
#pragma unroll
        for (int jj = 0; jj < 8; jj++) {
            float s = 0.f;
#pragma unroll
            for (int sp = 0; sp < 4; sp++) {
                float lo, hi; upk2(acc[jj][sp], lo, hi);
                s += fmaxf(lo, 0.f) + fmaxf(hi, 0.f);
            }
            jsum[jj] = s;
        }
#pragma unroll
        for (int jj = 0; jj < 8; jj++) {
            jsum[jj] += __shfl_xor_sync(FULL, jsum[jj], 1);
            jsum[jj] += __shfl_xor_sync(FULL, jsum[jj], 2);
        }
        if ((lane & 3) == 0) {
#pragma unroll
            for (int jj = 0; jj < 8; jj++) shb[j0 + jj] = jsum[jj] * (1.f / KN);
        }
        __syncwarp();

        // layer3 on the mean (mean commutes past linear W3): pm[64] -> pm_sh
        {
            float a0 = sm[OFF_B3 + lane], a1v = sm[OFF_B3 + lane + 32];
#pragma unroll 8
            for (int i = 0; i < 64; i++) {
                float hv = shb[i];
                a0  = fmaf(hv, sm[OFF_W3T + i * 68 + lane], a0);
                a1v = fmaf(hv, sm[OFF_W3T + i * 68 + lane + 32], a1v);
            }
            sm[OFF_PM + lane * 18 + w] = a0;
            sm[OFF_PM + (lane + 32) * 18 + w] = a1v;
        }

        // feature gather mean -> aggB[d][q*3+t]; lane owns elements 6*lane..6*lane+5
        {
            float2 fa0 = {0.f, 0.f}, fa1 = {0.f, 0.f}, fa2 = {0.f, 0.f};
#pragma unroll 4
            for (int k = 0; k < KN; k++) {
                int row = __shfl_sync(FULL, idxk, k);
                const float2* bb = (const float2*)(s_feats + (size_t)row * 192) + 3 * lane;
                float2 v0 = bb[0], v1 = bb[1], v2 = bb[2];
                fa0.x += v0.x; fa0.y += v0.y;
                fa1.x += v1.x; fa1.y += v1.y;
                fa2.x += v2.x; fa2.y += v2.y;
            }
            const float inv = 1.f / KN;
            float* ab = sm + OFF_AGG;
            int d0 = 2 * lane, cb = w * 3;
            ab[d0 * 50 + cb + 0] = fa0.x * inv;
            ab[d0 * 50 + cb + 1] = fa0.y * inv;
            ab[d0 * 50 + cb + 2] = fa1.x * inv;
            ab[(d0 + 1) * 50 + cb + 0] = fa1.y * inv;
            ab[(d0 + 1) * 50 + cb + 1] = fa2.x * inv;
            ab[(d0 + 1) * 50 + cb + 2] = fa2.y * inv;
        }
        __syncthreads();

        // ============ Phase B1: gate GEMM, warp w computes query w ============
        {
            const int ol = lane * 6;
            ull ga[3];
#pragma unroll
            for (int s = 0; s < 3; s++) ga[s] = *(const ull*)(sm + OFF_BG + ol + 2 * s);
#pragma unroll 4
            for (int j = 0; j < 64; j++) {
                float bvv = sm[OFF_PM + j * 18 + w];
                ull bp = pk2(bvv, bvv);
                const float* ar = sm + OFF_WGT + j * 196 + ol;
                ga[0] = fma2(*(const ull*)(ar + 0), bp, ga[0]);
                ga[1] = fma2(*(const ull*)(ar + 2), bp, ga[1]);
                ga[2] = fma2(*(const ull*)(ar + 4), bp, ga[2]);
            }
            float* gr = sm + OFF_GATE + w * 200 + ol;
#pragma unroll
            for (int s = 0; s < 3; s++) {
                float lo, hi; upk2(ga[s], lo, hi);
                float g0 = __fdividef(1.f, 1.f + __expf(-lo));
                float g1 = __fdividef(1.f, 1.f + __expf(-hi));
                *(float2*)(gr + 2 * s) = make_float2(g0, g1);
            }
        }
        __syncthreads();

        // ============ Phase B2: T = Wv @ agg, scale by gate, store ============
        {
            const int ol = w * 12 + (lane >> 3) * 3;   // 3 o per lane
            const int cl = (lane & 7) * 6;             // 6 c per lane (2 queries x 3)
            ull tac[3][3];
#pragma unroll
            for (int oo = 0; oo < 3; oo++)
#pragma unroll
                for (int s = 0; s < 3; s++) tac[oo][s] = 0ull;
#pragma unroll 4
            for (int d = 0; d < 64; d++) {
                const float* ar = sm + OFF_WVT + d * 196 + ol;
                const ull* br = (const ull*)(sm + OFF_AGG + d * 50 + cl);
                ull b0 = br[0], b1v = br[1], b2v = br[2];
#pragma unroll
                for (int oo = 0; oo < 3; oo++) {
                    float av = ar[oo];
                    ull ad = pk2(av, av);
                    tac[oo][0] = fma2(ad, b0, tac[oo][0]);
                    tac[oo][1] = fma2(ad, b1v, tac[oo][1]);
                    tac[oo][2] = fma2(ad, b2v, tac[oo][2]);
                }
            }
            const int lq = 2 * (lane & 7);
            const int gq0 = base + lq;
#pragma unroll
            for (int oo = 0; oo < 3; oo++) {
                const int o = ol + oo;
                float g0 = sm[OFF_GATE + lq * 200 + o];
                float g1 = sm[OFF_GATE + (lq + 1) * 200 + o];
                float v0, v1, v2, v3, v4, v5;
                upk2(tac[oo][0], v0, v1);   // c = cl+0 (q0,t0), cl+1 (q0,t1)
                upk2(tac[oo][1], v2, v3);   // cl+2 (q0,t2), cl+3 (q1,t0)
                upk2(tac[oo][2], v4, v5);   // cl+4 (q1,t1), cl+5 (q1,t2)
                float* ob0 = out + (size_t)gq0 * (OUTN * 3) + o * 3;
                float* ob1 = ob0 + (OUTN * 3);
                ob0[0] = v0 * g0; ob0[1] = v1 * g0; ob0[2] = v2 * g0;
                ob1[0] = v3 * g1; ob1[1] = v4 * g1; ob1[2] = v5 * g1;
            }
        }
        __syncthreads();   // protect pm/agg/gate before next tile
    }
}

extern "C" void kernel_launch(void* const* d_in, const int* in_sizes, int n_in,
                              void* d_out, int out_size) {
    const float* q_pts   = (const float*)d_in[0];
    const float* s_pts   = (const float*)d_in[1];
    const float* s_feats = (const float*)d_in[2];
    const int*   nbr     = (const int*)  d_in[3];
    const float* normals = (const float*)d_in[4];
    const float* W1 = (const float*)d_in[5];
    const float* b1 = (const float*)d_in[6];
    const float* W2 = (const float*)d_in[7];
    const float* b2 = (const float*)d_in[8];
    const float* W3 = (const float*)d_in[9];
    const float* b3 = (const float*)d_in[10];
    const float* Wg = (const float*)d_in[11];
    const float* bg = (const float*)d_in[12];
    const float* Wv = (const float*)d_in[13];
    float* out = (float*)d_out;

    static_assert(SM_FLOATS * 4 < 227 * 1024, "smem overflow");
    size_t smem = SM_FLOATS * sizeof(float);
    cudaFuncSetAttribute(ppf_attn_kernel,
                         cudaFuncAttributeMaxDynamicSharedMemorySize, (int)smem);

    ppf_attn_kernel<<<GRID, THREADS, smem>>>(
        q_pts, s_pts, s_feats, nbr, normals,
        W1, b1, W2, b2, W3, b3, Wg, bg, Wv, out);
}